// round 16
// baseline (speedup 1.0000x reference)
#include <cuda_runtime.h>
#include <cuda_fp16.h>
#include <math.h>
#include <stdint.h>

// ---------------- problem constants ----------------
#define B_     2
#define LQ_    21760
#define M_     (B_ * LQ_)      // 43520
#define C_     256
#define NHEAD_ 8
#define NS_    4
#define NL_    6
#define FF_    1024
#define NQKV   640             // 256 (v) + 256 (off) + 128 (att logits)

__device__ __constant__ int d_scH[4]   = {128, 64, 32, 16};
__device__ __constant__ int d_scW[4]   = {128, 64, 32, 16};
__device__ __constant__ int d_scSt[4]  = {0, 16384, 20480, 21504};

// ---------------- scratch (device globals; no allocation) ----------------
__device__ float  g_xp  [(size_t)M_ * C_];    // x+pos exact (residual 1)
__device__ __half g_xpH [(size_t)M_ * C_];    // fp16 xp (GEMM A)
__device__ float  g_qkv [(size_t)M_ * NQKV];  // off|logits fp32
__device__ __half g_vh  [(size_t)M_ * C_];    // fp16 value tensor
__device__ __half g_sampH[(size_t)M_ * C_];   // sampled value fp16 (Wo input)
__device__ float  g_x   [(size_t)M_ * C_];    // post-LN1 exact (residual 2)
__device__ __half g_xH  [(size_t)M_ * C_];    // fp16 post-LN1 (W1 input)
__device__ __half g_hH  [(size_t)M_ * FF_];   // FFN hidden fp16 (W2 input)
// fp16 weights [K][N]
__device__ __half g_wq  [(size_t)NL_ * C_ * NQKV];
__device__ float  g_bq  [(size_t)NL_ * NQKV];
__device__ __half g_wo  [(size_t)NL_ * C_ * C_];
__device__ __half g_w1  [(size_t)NL_ * C_ * FF_];
__device__ __half g_w2  [(size_t)NL_ * FF_ * C_];

// ---------------- weight prep ----------------
__global__ void tohalf_kernel(const float* __restrict__ src, __half* __restrict__ dst, int n4) {
    int i = blockIdx.x * blockDim.x + threadIdx.x;
    if (i >= n4) return;
    float4 v = ((const float4*)src)[i];
    ((__half2*)dst)[i * 2]     = __floats2half2_rn(v.x, v.y);
    ((__half2*)dst)[i * 2 + 1] = __floats2half2_rn(v.z, v.w);
}

__global__ void pack_qkv_kernel(const float* __restrict__ Wv, const float* __restrict__ Woff,
                                const float* __restrict__ Wat,
                                const float* __restrict__ bv, const float* __restrict__ boff,
                                const float* __restrict__ bat,
                                __half* __restrict__ wq, float* __restrict__ bq) {
    int idx = blockIdx.x * blockDim.x + threadIdx.x;
    const int total = NL_ * C_ * NQKV;
    if (idx < total) {
        const int c = idx % NQKV;
        const int k = (idx / NQKV) % C_;
        const int l = idx / (NQKV * C_);
        float v;
        if (c < 256)      v = Wv  [((size_t)l * C_ + k) * 256 + c];
        else if (c < 512) v = Woff[((size_t)l * C_ + k) * 256 + (c - 256)];
        else              v = Wat [((size_t)l * C_ + k) * 128 + (c - 512)];
        wq[idx] = __float2half(v);
    }
    if (idx < NL_ * NQKV) {
        const int c = idx % NQKV;
        const int l = idx / NQKV;
        float v;
        if (c < 256)      v = bv  [l * 256 + c];
        else if (c < 512) v = boff[l * 256 + (c - 256)];
        else              v = bat [l * 128 + (c - 512)];
        bq[idx] = v;
    }
}

// ---------------- layer-0 prep: xp = src + pos (fp32 + fp16) ----------------
__global__ void add0_kernel(const float* __restrict__ a, const float* __restrict__ b,
                            float* __restrict__ out, __half* __restrict__ outH, int n4) {
    int i = blockIdx.x * blockDim.x + threadIdx.x;
    if (i >= n4) return;
    float4 va = ((const float4*)a)[i];
    float4 vb = ((const float4*)b)[i];
    va.x += vb.x; va.y += vb.y; va.z += vb.z; va.w += vb.w;
    ((float4*)out)[i] = va;
    ((__half2*)outH)[i * 2]     = __floats2half2_rn(va.x, va.y);
    ((__half2*)outH)[i * 2 + 1] = __floats2half2_rn(va.z, va.w);
}

// ---------------- common helpers ----------------
__device__ __forceinline__ void cpa16h(__half* dst, const __half* src) {
    uint32_t d = (uint32_t)__cvta_generic_to_shared(dst);
    asm volatile("cp.async.cg.shared.global [%0], [%1], 16;" :: "r"(d), "l"(src));
}
__device__ __forceinline__ uint32_t s2u(const __half* p) {
    return (uint32_t)__cvta_generic_to_shared(p);
}

// ---------------- fp16 GEMM (m16n8k16) 128x128 tile (qkv, W1) --------------
#define BM 128
#define BN 128
#define BK 32
#define ASTR 40
#define BSTR 136
#define ASZ_H (BM * ASTR)
#define BSZ_H (BK * BSTR)
#define STAGE_H (ASZ_H + BSZ_H)
#define NSTAGE 3
#define GEMM_SMEM (NSTAGE * STAGE_H * 2)   // 56832 B

// mode: 0 = fp32 out; 1 = fp16 out; 2 = qkv split (col<256 -> fp16 vh stride 256)
__global__ __launch_bounds__(128, 2)
void h16gemm_kernel(const __half* __restrict__ A, const __half* __restrict__ W,
                    const float* __restrict__ bias, float* __restrict__ Cout,
                    __half* __restrict__ Hout,
                    int N, int Kd, int relu, int mode) {
    extern __shared__ __align__(16) __half smh[];

    const int tid  = threadIdx.x;
    const int warp = tid >> 5;
    const int lane = tid & 31;
    const int m0 = (warp >> 1) * 64;
    const int n0 = (warp & 1) * 64;
    const int bx = blockIdx.x, by = blockIdx.y;

    const int alr = tid >> 2;
    const int alc = (tid & 3) * 8;
    const int blr = tid >> 4;
    const int blc = (tid & 15) * 8;

    const __half* Ag = A + (size_t)(by * BM) * Kd;
    const __half* Wg = W + (size_t)bx * BN;

    float acc[4][8][4];
#pragma unroll
    for (int mi = 0; mi < 4; mi++)
#pragma unroll
        for (int nf = 0; nf < 8; nf++)
#pragma unroll
            for (int r = 0; r < 4; r++) acc[mi][nf][r] = 0.f;

    const int NK = Kd / BK;

#pragma unroll
    for (int s = 0; s < 2; s++) {
        if (s < NK) {
            __half* as = smh + s * STAGE_H;
            __half* bs = as + ASZ_H;
            const int k0 = s * BK;
#pragma unroll
            for (int p = 0; p < 4; p++) {
                const int row = p * 32 + alr;
                cpa16h(as + row * ASTR + alc, Ag + (size_t)row * Kd + k0 + alc);
            }
#pragma unroll
            for (int p = 0; p < 4; p++) {
                const int row = p * 8 + blr;
                cpa16h(bs + row * BSTR + blc, Wg + (size_t)(k0 + row) * N + blc);
            }
            asm volatile("cp.async.commit_group;");
        }
    }

    const int amat = lane >> 3;
    const int arow = lane & 7;
    const int bl   = lane & 15;
    const int bmat = bl >> 3;
    const int brow = bl & 7;

    for (int i = 0; i < NK; i++) {
        if (i + 1 < NK) asm volatile("cp.async.wait_group 1;");
        else            asm volatile("cp.async.wait_group 0;");
        __syncthreads();

        if (i + 2 < NK) {
            const int k0 = (i + 2) * BK;
            __half* as = smh + ((i + 2) % NSTAGE) * STAGE_H;
            __half* bs = as + ASZ_H;
#pragma unroll
            for (int p = 0; p < 4; p++) {
                const int row = p * 32 + alr;
                cpa16h(as + row * ASTR + alc, Ag + (size_t)row * Kd + k0 + alc);
            }
#pragma unroll
            for (int p = 0; p < 4; p++) {
                const int row = p * 8 + blr;
                cpa16h(bs + row * BSTR + blc, Wg + (size_t)(k0 + row) * N + blc);
            }
            asm volatile("cp.async.commit_group;");
        }

        const __half* as = smh + (i % NSTAGE) * STAGE_H;
        const __half* bs = as + ASZ_H;

#pragma unroll
        for (int kk = 0; kk < BK; kk += 16) {
            uint32_t a[4][4], b[8][2];
#pragma unroll
            for (int mi = 0; mi < 4; mi++) {
                const int r = m0 + mi * 16 + (amat & 1) * 8 + arow;
                const int c = kk + (amat >> 1) * 8;
                const uint32_t addr = s2u(as + r * ASTR + c);
                asm volatile("ldmatrix.sync.aligned.m8n8.x4.shared.b16 {%0,%1,%2,%3}, [%4];"
                             : "=r"(a[mi][0]), "=r"(a[mi][1]), "=r"(a[mi][2]), "=r"(a[mi][3])
                             : "r"(addr));
            }
#pragma unroll
            for (int nf = 0; nf < 8; nf++) {
                const int r = kk + bmat * 8 + brow;
                const int c = n0 + nf * 8;
                const uint32_t addr = s2u(bs + r * BSTR + c);
                asm volatile("ldmatrix.sync.aligned.m8n8.x2.trans.shared.b16 {%0,%1}, [%2];"
                             : "=r"(b[nf][0]), "=r"(b[nf][1]) : "r"(addr));
            }
#pragma unroll
            for (int mi = 0; mi < 4; mi++)
#pragma unroll
                for (int nf = 0; nf < 8; nf++) {
                    asm volatile(
                        "mma.sync.aligned.m16n8k16.row.col.f32.f16.f16.f32 "
                        "{%0,%1,%2,%3}, {%4,%5,%6,%7}, {%8,%9}, {%0,%1,%2,%3};"
                        : "+f"(acc[mi][nf][0]), "+f"(acc[mi][nf][1]),
                          "+f"(acc[mi][nf][2]), "+f"(acc[mi][nf][3])
                        : "r"(a[mi][0]), "r"(a[mi][1]), "r"(a[mi][2]), "r"(a[mi][3]),
                          "r"(b[nf][0]), "r"(b[nf][1]));
                }
        }
    }

    const int gr = lane >> 2;
    const int gc = (lane & 3) * 2;
#pragma unroll
    for (int mi = 0; mi < 4; mi++) {
#pragma unroll
        for (int nf = 0; nf < 8; nf++) {
            const int col = bx * BN + n0 + nf * 8 + gc;
            const float b0 = bias[col], b1 = bias[col + 1];
            const int row0 = by * BM + m0 + mi * 16 + gr;

            float2 v0 = make_float2(acc[mi][nf][0] + b0, acc[mi][nf][1] + b1);
            float2 v1 = make_float2(acc[mi][nf][2] + b0, acc[mi][nf][3] + b1);
            if (relu) {
                v0.x = fmaxf(v0.x, 0.f); v0.y = fmaxf(v0.y, 0.f);
                v1.x = fmaxf(v1.x, 0.f); v1.y = fmaxf(v1.y, 0.f);
            }
            if (mode == 1 || (mode == 2 && col < 256)) {
                const int hstride = (mode == 2) ? 256 : N;
                *(__half2*)(Hout + (size_t)row0 * hstride + col)       = __floats2half2_rn(v0.x, v0.y);
                *(__half2*)(Hout + (size_t)(row0 + 8) * hstride + col) = __floats2half2_rn(v1.x, v1.y);
            } else {
                *(float2*)(Cout + (size_t)row0 * N + col)       = v0;
                *(float2*)(Cout + (size_t)(row0 + 8) * N + col) = v1;
            }
        }
    }
}

// ---------------- fused fp16 GEMM (N=256) + residual + LayerNorm -----------
// 64x256 tile, 256 threads (8 warps a 32x64). Epilogue: acc+bias -> smem tile,
// then per-warp LN over full 256-col rows (identical math to prior ln_kernel).
#define FBM 64
#define FBN 256
#define FASTR 40
#define FBSTR 264
#define FASZ (FBM * FASTR)             // 2560 halves
#define FBSZ (BK * FBSTR)              // 8448 halves
#define FSTAGE (FASZ + FBSZ)           // 11008 halves = 22016 B
#define FTILE_STRIDE 260
#define FUSED_SMEM 66560               // max(3*22016, 64*260*4) = 66560 B

__global__ __launch_bounds__(256, 2)
void h16gemm_ln_kernel(const __half* __restrict__ A, const __half* __restrict__ W,
                       const float* __restrict__ bias,
                       const float* __restrict__ resid,
                       const float* __restrict__ gamma, const float* __restrict__ beta,
                       const float* __restrict__ pos,
                       float* __restrict__ outF, __half* __restrict__ outH,
                       int Kd) {
    extern __shared__ __align__(16) __half smh[];
    float* tile = (float*)smh;

    const int tid  = threadIdx.x;
    const int warp = tid >> 5;
    const int lane = tid & 31;
    const int m0 = (warp >> 2) * 32;     // 2 m-warps
    const int n0 = (warp & 3) * 64;      // 4 n-warps
    const int by = blockIdx.y;

    const int alr = tid >> 2;            // 0..63
    const int alc = (tid & 3) * 8;
    const int blr = tid >> 3;            // 0..31
    const int blc8 = (tid & 7) * 8;

    const __half* Ag = A + (size_t)(by * FBM) * Kd;
    const __half* Wg = W;                // N = 256 = FBN, single x-block

    float acc[2][8][4];
#pragma unroll
    for (int mi = 0; mi < 2; mi++)
#pragma unroll
        for (int nf = 0; nf < 8; nf++)
#pragma unroll
            for (int r = 0; r < 4; r++) acc[mi][nf][r] = 0.f;

    const int NK = Kd / BK;

#pragma unroll
    for (int s = 0; s < 2; s++) {
        if (s < NK) {
            __half* as = smh + s * FSTAGE;
            __half* bs = as + FASZ;
            const int k0 = s * BK;
            cpa16h(as + alr * FASTR + alc, Ag + (size_t)alr * Kd + k0 + alc);
#pragma unroll
            for (int p = 0; p < 4; p++) {
                const int col = p * 64 + blc8;
                cpa16h(bs + blr * FBSTR + col, Wg + (size_t)(k0 + blr) * FBN + col);
            }
            asm volatile("cp.async.commit_group;");
        }
    }

    const int amat = lane >> 3;
    const int arow = lane & 7;
    const int bl   = lane & 15;
    const int bmat = bl >> 3;
    const int brow = bl & 7;

    for (int i = 0; i < NK; i++) {
        if (i + 1 < NK) asm volatile("cp.async.wait_group 1;");
        else            asm volatile("cp.async.wait_group 0;");
        __syncthreads();

        if (i + 2 < NK) {
            const int k0 = (i + 2) * BK;
            __half* as = smh + ((i + 2) % NSTAGE) * FSTAGE;
            __half* bs = as + FASZ;
            cpa16h(as + alr * FASTR + alc, Ag + (size_t)alr * Kd + k0 + alc);
#pragma unroll
            for (int p = 0; p < 4; p++) {
                const int col = p * 64 + blc8;
                cpa16h(bs + blr * FBSTR + col, Wg + (size_t)(k0 + blr) * FBN + col);
            }
            asm volatile("cp.async.commit_group;");
        }

        const __half* as = smh + (i % NSTAGE) * FSTAGE;
        const __half* bs = as + FASZ;

#pragma unroll
        for (int kk = 0; kk < BK; kk += 16) {
            uint32_t a[2][4], b[8][2];
#pragma unroll
            for (int mi = 0; mi < 2; mi++) {
                const int r = m0 + mi * 16 + (amat & 1) * 8 + arow;
                const int c = kk + (amat >> 1) * 8;
                const uint32_t addr = s2u(as + r * FASTR + c);
                asm volatile("ldmatrix.sync.aligned.m8n8.x4.shared.b16 {%0,%1,%2,%3}, [%4];"
                             : "=r"(a[mi][0]), "=r"(a[mi][1]), "=r"(a[mi][2]), "=r"(a[mi][3])
                             : "r"(addr));
            }
#pragma unroll
            for (int nf = 0; nf < 8; nf++) {
                const int r = kk + bmat * 8 + brow;
                const int c = n0 + nf * 8;
                const uint32_t addr = s2u(bs + r * FBSTR + c);
                asm volatile("ldmatrix.sync.aligned.m8n8.x2.trans.shared.b16 {%0,%1}, [%2];"
                             : "=r"(b[nf][0]), "=r"(b[nf][1]) : "r"(addr));
            }
#pragma unroll
            for (int mi = 0; mi < 2; mi++)
#pragma unroll
                for (int nf = 0; nf < 8; nf++) {
                    asm volatile(
                        "mma.sync.aligned.m16n8k16.row.col.f32.f16.f16.f32 "
                        "{%0,%1,%2,%3}, {%4,%5,%6,%7}, {%8,%9}, {%0,%1,%2,%3};"
                        : "+f"(acc[mi][nf][0]), "+f"(acc[mi][nf][1]),
                          "+f"(acc[mi][nf][2]), "+f"(acc[mi][nf][3])
                        : "r"(a[mi][0]), "r"(a[mi][1]), "r"(a[mi][2]), "r"(a[mi][3]),
                          "r"(b[nf][0]), "r"(b[nf][1]));
                }
        }
    }

    // stage acc + bias into smem tile (reuses stage smem; all cp.async drained)
    __syncthreads();
    const int gr = lane >> 2;
    const int gc = (lane & 3) * 2;
#pragma unroll
    for (int mi = 0; mi < 2; mi++) {
#pragma unroll
        for (int nf = 0; nf < 8; nf++) {
            const int col = n0 + nf * 8 + gc;
            const float b0 = bias[col], b1 = bias[col + 1];
            const int r0 = m0 + mi * 16 + gr;
            tile[(size_t)r0 * FTILE_STRIDE + col]           = acc[mi][nf][0] + b0;
            tile[(size_t)r0 * FTILE_STRIDE + col + 1]       = acc[mi][nf][1] + b1;
            tile[(size_t)(r0 + 8) * FTILE_STRIDE + col]     = acc[mi][nf][2] + b0;
            tile[(size_t)(r0 + 8) * FTILE_STRIDE + col + 1] = acc[mi][nf][3] + b1;
        }
    }
    __syncthreads();

    // per-warp LayerNorm over 8 rows each
    const int c = lane * 8;
    float4 g0 = *(const float4*)(gamma + c);
    float4 g1 = *(const float4*)(gamma + c + 4);
    float4 t0 = *(const float4*)(beta + c);
    float4 t1 = *(const float4*)(beta + c + 4);

#pragma unroll
    for (int rr = 0; rr < 8; rr++) {
        const int r = warp * 8 + rr;
        const size_t base = (size_t)(by * FBM + r) * C_ + c;
        const float* tr = tile + (size_t)r * FTILE_STRIDE + c;
        float4 v0t = *(const float4*)(tr);
        float4 v1t = *(const float4*)(tr + 4);
        float4 r0 = *(const float4*)(resid + base);
        float4 r1 = *(const float4*)(resid + base + 4);
        float vals[8];
        vals[0] = r0.x + v0t.x; vals[1] = r0.y + v0t.y;
        vals[2] = r0.z + v0t.z; vals[3] = r0.w + v0t.w;
        vals[4] = r1.x + v1t.x; vals[5] = r1.y + v1t.y;
        vals[6] = r1.z + v1t.z; vals[7] = r1.w + v1t.w;

        float s = 0.f;
#pragma unroll
        for (int i = 0; i < 8; i++) s += vals[i];
#pragma unroll
        for (int o = 16; o > 0; o >>= 1) s += __shfl_xor_sync(0xffffffffu, s, o);
        const float mean = s * (1.f / 256.f);
        float vs = 0.f;
#pragma unroll
        for (int i = 0; i < 8; i++) {
            const float dlt = vals[i] - mean;
            vs += dlt * dlt;
        }
#pragma unroll
        for (int o = 16; o > 0; o >>= 1) vs += __shfl_xor_sync(0xffffffffu, vs, o);
        const float rstd = rsqrtf(vs * (1.f / 256.f) + 1e-5f);

        float o[8];
        o[0] = (vals[0] - mean) * rstd * g0.x + t0.x;
        o[1] = (vals[1] - mean) * rstd * g0.y + t0.y;
        o[2] = (vals[2] - mean) * rstd * g0.z + t0.z;
        o[3] = (vals[3] - mean) * rstd * g0.w + t0.w;
        o[4] = (vals[4] - mean) * rstd * g1.x + t1.x;
        o[5] = (vals[5] - mean) * rstd * g1.y + t1.y;
        o[6] = (vals[6] - mean) * rstd * g1.z + t1.z;
        o[7] = (vals[7] - mean) * rstd * g1.w + t1.w;

        if (pos) {
            float4 p0 = *(const float4*)(pos + base);
            float4 p1 = *(const float4*)(pos + base + 4);
            o[0] += p0.x; o[1] += p0.y; o[2] += p0.z; o[3] += p0.w;
            o[4] += p1.x; o[5] += p1.y; o[6] += p1.z; o[7] += p1.w;
        }
        *(float4*)(outF + base)     = make_float4(o[0], o[1], o[2], o[3]);
        *(float4*)(outF + base + 4) = make_float4(o[4], o[5], o[6], o[7]);
        if (outH) {
            *(__half2*)(outH + base)     = __floats2half2_rn(o[0], o[1]);
            *(__half2*)(outH + base + 2) = __floats2half2_rn(o[2], o[3]);
            *(__half2*)(outH + base + 4) = __floats2half2_rn(o[4], o[5]);
            *(__half2*)(outH + base + 6) = __floats2half2_rn(o[6], o[7]);
        }
    }
}

// ---------------- deformable sampling (unchanged from R12) -----------------
__global__ __launch_bounds__(256, 4)
void deform_kernel(const float* __restrict__ qkv,
                   const __half* __restrict__ vh,
                   const float* __restrict__ ref,
                   __half* __restrict__ out) {
    const int warp = threadIdx.x >> 5;
    const int lane = threadIdx.x & 31;
    const int q = blockIdx.x * 8 + warp;
    const int h = lane >> 2;
    const int cg = lane & 3;
    const int b = q / LQ_;

    const float* lg = qkv + (size_t)q * NQKV + 512 + h * 16;
    const float4 lv = *(const float4*)(lg + cg * 4);
    float mx = fmaxf(fmaxf(lv.x, lv.y), fmaxf(lv.z, lv.w));
    mx = fmaxf(mx, __shfl_xor_sync(0xffffffffu, mx, 1));
    mx = fmaxf(mx, __shfl_xor_sync(0xffffffffu, mx, 2));
    float e[4];
    e[0] = __expf(lv.x - mx);
    e[1] = __expf(lv.y - mx);
    e[2] = __expf(lv.z - mx);
    e[3] = __expf(lv.w - mx);
    float s = e[0] + e[1] + e[2] + e[3];
    s += __shfl_xor_sync(0xffffffffu, s, 1);
    s += __shfl_xor_sync(0xffffffffu, s, 2);
    const float inv = 1.f / s;
    const int quad = lane & ~3;

    const float rx = ref[(size_t)q * 2 + 0];
    const float ry = ref[(size_t)q * 2 + 1];
    const float* offq = qkv + (size_t)q * NQKV + 256 + h * 32;

    float acc[8];
#pragma unroll
    for (int c = 0; c < 8; c++) acc[c] = 0.f;

#pragma unroll
    for (int l = 0; l < 4; l++) {
        const int Hl = d_scH[l], Wl = d_scW[l], st = d_scSt[l];
        const float invW = 1.f / (float)Wl, invH = 1.f / (float)Hl;
        const float Wm1 = (float)(Wl - 1), Hm1 = (float)(Hl - 1);
        const __half* vl = vh + (size_t)(b * LQ_ + st) * 256 + h * 32 + cg * 8;
#pragma unroll
        for (int k = 0; k < 4; k++) {
            const int idx = l * 4 + k;
            const float2 oxy = *(const float2*)(offq + idx * 2);
            const float ww = __shfl_sync(0xffffffffu, e[idx & 3], quad + (idx >> 2)) * inv;
            float x = (rx + oxy.x * invW) * Wm1;
            float y = (ry + oxy.y * invH) * Hm1;
            x = fminf(fmaxf(x, 0.f), Wm1);
            y = fminf(fmaxf(y, 0.f), Hm1);
            const float x0f = floorf(x), y0f = floorf(y);
            const int x0 = (int)x0f, y0 = (int)y0f;
            const int x1 = min(x0 + 1, Wl - 1), y1 = min(y0 + 1, Hl - 1);
            const float wx = x - x0f, wy = y - y0f;

            uint4 r00 = *(const uint4*)(vl + (size_t)(y0 * Wl + x0) * 256);
            uint4 r01 = *(const uint4*)(vl + (size_t)(y0 * Wl + x1) * 256);
            uint4 r10 = *(const uint4*)(vl + (size_t)(y1 * Wl + x0) * 256);
            uint4 r11 = *(const uint4*)(vl + (size_t)(y1 * Wl + x1) * 256);

            const uint32_t* p00 = (const uint32_t*)&r00;
            const uint32_t* p01 = (const uint32_t*)&r01;
            const uint32_t* p10 = (const uint32_t*)&r10;
            const uint32_t* p11 = (const uint32_t*)&r11;
#pragma unroll
            for (int c2 = 0; c2 < 4; c2++) {
                float2 f00 = __half22float2(*(const __half2*)&p00[c2]);
                float2 f01 = __half22float2(*(const __half2*)&p01[c2]);
                float2 f10 = __half22float2(*(const __half2*)&p10[c2]);
                float2 f11 = __half22float2(*(const __half2*)&p11[c2]);
                float top, bot;
                top = f00.x + wx * (f01.x - f00.x);
                bot = f10.x + wx * (f11.x - f10.x);
                acc[c2 * 2]     = fmaf(ww, top + wy * (bot - top), acc[c2 * 2]);
                top = f00.y + wx * (f01.y - f00.y);
                bot = f10.y + wx * (f11.y - f10.y);
                acc[c2 * 2 + 1] = fmaf(ww, top + wy * (bot - top), acc[c2 * 2 + 1]);
            }
        }
    }

    uint4 st4;
    uint32_t* sp = (uint32_t*)&st4;
#pragma unroll
    for (int c2 = 0; c2 < 4; c2++) {
        __half2 hh = __floats2half2_rn(acc[c2 * 2], acc[c2 * 2 + 1]);
        sp[c2] = *(uint32_t*)&hh;
    }
    *(uint4*)(out + (size_t)q * C_ + h * 32 + cg * 8) = st4;
}

// ---------------- launch ----------------
extern "C" void kernel_launch(void* const* d_in, const int* in_sizes, int n_in,
                              void* d_out, int out_size) {
    const float* src  = (const float*)d_in[0];
    const float* pos  = (const float*)d_in[1];
    const float* ref  = (const float*)d_in[2];
    const float* Woff = (const float*)d_in[3];
    const float* boff = (const float*)d_in[4];
    const float* Wat  = (const float*)d_in[5];
    const float* bat  = (const float*)d_in[6];
    const float* Wv   = (const float*)d_in[7];
    const float* bv   = (const float*)d_in[8];
    const float* Wo   = (const float*)d_in[9];
    const float* bo   = (const float*)d_in[10];
    const float* W1   = (const float*)d_in[11];
    const float* b1   = (const float*)d_in[12];
    const float* W2   = (const float*)d_in[13];
    const float* b2   = (const float*)d_in[14];
    const float* n1s  = (const float*)d_in[15];
    const float* n1b  = (const float*)d_in[16];
    const float* n2s  = (const float*)d_in[17];
    const float* n2b  = (const float*)d_in[18];
    float* outp = (float*)d_out;

    float *xp, *qkv, *x, *bq;
    __half *xpH, *vh, *sampH, *xH, *hH, *wq, *wo, *w1, *w2;
    cudaGetSymbolAddress((void**)&xp,    g_xp);
    cudaGetSymbolAddress((void**)&xpH,   g_xpH);
    cudaGetSymbolAddress((void**)&qkv,   g_qkv);
    cudaGetSymbolAddress((void**)&vh,    g_vh);
    cudaGetSymbolAddress((void**)&sampH, g_sampH);
    cudaGetSymbolAddress((void**)&x,     g_x);
    cudaGetSymbolAddress((void**)&xH,    g_xH);
    cudaGetSymbolAddress((void**)&hH,    g_hH);
    cudaGetSymbolAddress((void**)&wq,    g_wq);
    cudaGetSymbolAddress((void**)&bq,    g_bq);
    cudaGetSymbolAddress((void**)&wo,    g_wo);
    cudaGetSymbolAddress((void**)&w1,    g_w1);
    cudaGetSymbolAddress((void**)&w2,    g_w2);

    cudaFuncSetAttribute(h16gemm_kernel,
                         cudaFuncAttributeMaxDynamicSharedMemorySize, GEMM_SMEM);
    cudaFuncSetAttribute(h16gemm_ln_kernel,
                         cudaFuncAttributeMaxDynamicSharedMemorySize, FUSED_SMEM);

    // weight prep
    {
        const int nq = NL_ * C_ * NQKV;
        pack_qkv_kernel<<<(nq + 255) / 256, 256>>>(Wv, Woff, Wat, bv, boff, bat, wq, bq);
        const int n_wo = NL_ * C_ * C_ / 4;
        tohalf_kernel<<<(n_wo + 255) / 256, 256>>>(Wo, wo, n_wo);
        const int n_w1 = NL_ * C_ * FF_ / 4;
        tohalf_kernel<<<(n_w1 + 255) / 256, 256>>>(W1, w1, n_w1);
        const int n_w2 = NL_ * FF_ * C_ / 4;
        tohalf_kernel<<<(n_w2 + 255) / 256, 256>>>(W2, w2, n_w2);
    }

    const int n4 = M_ * C_ / 4;
    const dim3 gQKV(5, M_ / BM);
    const dim3 gN1024(8, M_ / BM);
    const dim3 gFused(1, M_ / FBM);

    add0_kernel<<<(n4 + 255) / 256, 256>>>(src, pos, xp, xpH, n4);

    for (int i = 0; i < NL_; i++) {
        // qkv: v cols -> fp16 vh; off/logits -> fp32 qkv
        h16gemm_kernel<<<gQKV, 128, GEMM_SMEM>>>(xpH, wq + (size_t)i * C_ * NQKV,
                                                 bq + (size_t)i * NQKV, qkv, vh, NQKV, C_, 0, 2);
        deform_kernel<<<M_ / 8, 256>>>(qkv, vh, ref, sampH);
        // x = LN(xp + samp@Wo + bo) -> fp32 x + fp16 xH   (fused)
        h16gemm_ln_kernel<<<gFused, 256, FUSED_SMEM>>>(sampH, wo + (size_t)i * C_ * C_,
                                                       bo + (size_t)i * C_, xp,
                                                       n1s + (size_t)i * C_, n1b + (size_t)i * C_,
                                                       (const float*)nullptr, x, xH, C_);
        // h = relu(x @ W1 + b1) -> fp16
        h16gemm_kernel<<<gN1024, 128, GEMM_SMEM>>>(xH, w1 + (size_t)i * C_ * FF_,
                                                   b1 + (size_t)i * FF_, (float*)nullptr, hH, FF_, C_, 1, 1);
        // LN2 fused: xp = LN(x + h@W2 + b2) [+pos] ; last layer -> outp only
        if (i == NL_ - 1) {
            h16gemm_ln_kernel<<<gFused, 256, FUSED_SMEM>>>(hH, w2 + (size_t)i * FF_ * C_,
                                                           b2 + (size_t)i * C_, x,
                                                           n2s + (size_t)i * C_, n2b + (size_t)i * C_,
                                                           (const float*)nullptr, outp, (__half*)nullptr, FF_);
        } else {
            h16gemm_ln_kernel<<<gFused, 256, FUSED_SMEM>>>(hH, w2 + (size_t)i * FF_ * C_,
                                                           b2 + (size_t)i * C_, x,
                                                           n2s + (size_t)i * C_, n2b + (size_t)i * C_,
                                                           pos, xp, xpH, FF_);
        }
    }
    (void)in_sizes; (void)n_in; (void)out_size;
}